// round 7
// baseline (speedup 1.0000x reference)
#include <cuda_runtime.h>
#include <cstdint>

#define Hs 96
#define Is 100
#define Ts 512
#define Bs 512
#define Gs 288               // 3*H
#define Ms (Ts*Bs)           // 262144 rows
#define NB 7                 // batches per scan CTA

// Scratch for input projections: [dir][m][g]
__device__ float g_xproj[2][(size_t)Ms * Gs];

typedef unsigned long long u64;

__device__ __forceinline__ u64 fma2(u64 a, u64 b, u64 c) {
    u64 d;
    asm("fma.rn.f32x2 %0, %1, %2, %3;" : "=l"(d) : "l"(a), "l"(b), "l"(c));
    return d;
}
__device__ __forceinline__ float hsum2(u64 a) {
    float x, y;
    asm("mov.b64 {%0,%1}, %2;" : "=f"(x), "=f"(y) : "l"(a));
    return x + y;
}
__device__ __forceinline__ float sigm(float x) {
    return __fdividef(1.0f, 1.0f + __expf(-x));
}
__device__ __forceinline__ float tanh_(float x) {
    return 1.0f - __fdividef(2.0f, 1.0f + __expf(2.0f * x));
}

// ---------------------------------------------------------------------------
// Input projection. Tile 128 m-rows x 96 g-cols, K=100. 512 threads,
// thread tile 8x3. grid=(6, 2048): blockIdx.x = gtile + 3*dir fastest so the
// 6 CTAs sharing an x-tile are schedule-adjacent (x from L2).
// Dynamic smem 89.6KB -> 1 CTA/SM, 16 warps.
// ---------------------------------------------------------------------------
__global__ __launch_bounds__(512, 1) void proj_kernel(
    const float* __restrict__ x,
    const float* __restrict__ wf, const float* __restrict__ bf,
    const float* __restrict__ wb, const float* __restrict__ bb)
{
    extern __shared__ float psm[];
    float* xs = psm;                  // [128][100]
    float* ws = psm + 128 * Is;       // [96][100]

    const int bx = blockIdx.x;
    const int dir = (bx >= 3);
    const int g0 = (dir ? bx - 3 : bx) * 96;
    const size_t m0 = (size_t)blockIdx.y * 128;
    const int tid = threadIdx.x;

    const float* __restrict__ w    = dir ? wb : wf;
    const float* __restrict__ bias = dir ? bb : bf;

    // Vectorized tile loads (source regions contiguous + 16B aligned)
    {
        const float4* xsrc = (const float4*)(x + m0 * Is);
        float4* xd = (float4*)xs;
        for (int i = tid; i < 128 * Is / 4; i += 512) xd[i] = xsrc[i];
        const float4* wsrc = (const float4*)(w + (size_t)g0 * Is);
        float4* wd = (float4*)ws;
        for (int i = tid; i < 96 * Is / 4; i += 512) wd[i] = wsrc[i];
    }
    __syncthreads();

    const int cg = tid & 31;   // col group: cols cg + 32*c
    const int rg = tid >> 5;   // row group: rows rg*8 + r

    u64 acc[8][3];
    #pragma unroll
    for (int r = 0; r < 8; r++)
        #pragma unroll
        for (int c = 0; c < 3; c++) acc[r][c] = 0ull;

    #pragma unroll 5
    for (int k4 = 0; k4 < 25; k4++) {            // 4 k-values per iter
        ulonglong2 wv[3];
        #pragma unroll
        for (int c = 0; c < 3; c++)
            wv[c] = *(const ulonglong2*)&ws[(cg + 32 * c) * Is + 4 * k4];
        #pragma unroll
        for (int r = 0; r < 8; r++) {
            const ulonglong2 xv = *(const ulonglong2*)&xs[(rg * 8 + r) * Is + 4 * k4];
            #pragma unroll
            for (int c = 0; c < 3; c++) {
                acc[r][c] = fma2(xv.x, wv[c].x, acc[r][c]);
                acc[r][c] = fma2(xv.y, wv[c].y, acc[r][c]);
            }
        }
    }

    #pragma unroll
    for (int c = 0; c < 3; c++) {
        const int gcol = g0 + cg + 32 * c;
        const float bv = __ldg(&bias[gcol]);
        #pragma unroll
        for (int r = 0; r < 8; r++) {
            const size_t m = m0 + rg * 8 + r;
            g_xproj[dir][m * Gs + gcol] = hsum2(acc[r][c]) + bv;
        }
    }
}

// ---------------------------------------------------------------------------
// Recurrent scan. 148 CTAs (74 overlapping batch-groups of 7 x 2 dirs),
// 576 threads = 18 warps (5/5/4/4 per SMSP). Thread = (g, half):
// g = tid>>1 owns gate row g, half = tid&1 owns k-range [48*half, 48*half+48)
// of W_hh row g in 24 u64 REGISTERS. Lane pairs (2k, 2k+1) share g ->
// shfl.bfly(1) combines the two half-dot-products.
// h in smem, read warp-uniform-per-half (2 addrs/warp, different banks).
// r/z rows activate their own sigmoid (half 0 publishes); n rows keep hp_n in
// regs, finalize tanh + state update with batches split across the two halves.
// ---------------------------------------------------------------------------
__global__ __launch_bounds__(576, 1) void scan_kernel(
    const float* __restrict__ whf, const float* __restrict__ bhf,
    const float* __restrict__ whb, const float* __restrict__ bhb,
    float* __restrict__ out)
{
    __shared__ __align__(16) float hsh[NB][Hs];  // hidden state
    __shared__ float rz[NB][2 * Hs];             // activated r [0,96), z [96,192)

    const int tid  = threadIdx.x;
    const int g    = tid >> 1;                   // gate row 0..287
    const int half = tid & 1;                    // k-half
    const int dir  = blockIdx.x & 1;
    const int gi   = blockIdx.x >> 1;            // 0..73
    int b0 = 7 * gi; if (b0 > Bs - NB) b0 = Bs - NB;   // overlap-pad last group

    const float* __restrict__ wh = dir ? whb : whf;
    const float* __restrict__ bh = dir ? bhb : bhf;

    // Half of W_hh row g -> 24 u64 registers
    u64 w2[24];
    {
        const u64* wrow = (const u64*)(wh + g * Hs + 48 * half);
        #pragma unroll
        for (int j = 0; j < 24; j++) w2[j] = __ldg(&wrow[j]);
    }
    const float bhv = __ldg(&bh[g]);

    for (int i = tid; i < NB * Hs; i += 576) (&hsh[0][0])[i] = 0.0f;

    const float* __restrict__ xpb = g_xproj[dir];
    const int t_first = dir ? (Ts - 1) : 0;
    const int tstep   = dir ? -1 : 1;

    const bool is_n = (g >= 2 * Hs);
    const int  in   = g - 2 * Hs;

    float xc[NB], xn[NB];
    #pragma unroll
    for (int bb = 0; bb < NB; bb++)
        xc[bb] = __ldg(&xpb[((size_t)t_first * Bs + b0 + bb) * Gs + g]);

    __syncthreads();

    int tt = t_first;
    #pragma unroll 1
    for (int t = 0; t < Ts; t++) {
        // Prefetch next step's xp
        const int tn = (t == Ts - 1) ? tt : (tt + tstep);
        #pragma unroll
        for (int bb = 0; bb < NB; bb++)
            xn[bb] = __ldg(&xpb[((size_t)tn * Bs + b0 + bb) * Gs + g]);

        // Stage 1: half-matvec, NB independent fma2 chains
        u64 acc[NB];
        #pragma unroll
        for (int bb = 0; bb < NB; bb++) acc[bb] = 0ull;
        #pragma unroll
        for (int j = 0; j < 12; j++) {
            ulonglong2 hv[NB];
            #pragma unroll
            for (int bb = 0; bb < NB; bb++)
                hv[bb] = *(const ulonglong2*)&hsh[bb][48 * half + 4 * j];
            #pragma unroll
            for (int bb = 0; bb < NB; bb++) {
                acc[bb] = fma2(w2[2 * j],     hv[bb].x, acc[bb]);
                acc[bb] = fma2(w2[2 * j + 1], hv[bb].y, acc[bb]);
            }
        }

        // Combine halves: lane pairs (2k, 2k+1) share g
        float dot[NB];
        #pragma unroll
        for (int bb = 0; bb < NB; bb++) {
            const float p = hsum2(acc[bb]);
            dot[bb] = p + __shfl_xor_sync(0xFFFFFFFFu, p, 1) + bhv;
        }

        // Stage 2: r/z rows activate their own sigmoid (half 0 publishes)
        float hpn[NB];
        if (!is_n) {
            if (half == 0) {
                #pragma unroll
                for (int bb = 0; bb < NB; bb++)
                    rz[bb][g] = sigm(xc[bb] + dot[bb]);
            }
        } else {
            #pragma unroll
            for (int bb = 0; bb < NB; bb++) hpn[bb] = dot[bb];
        }
        __syncthreads();

        // Stage 3: n rows finalize; batches split across halves (4 + 3)
        if (is_n) {
            const int blo = half ? 4 : 0;
            const int bhi = half ? NB : 4;
            for (int bb = blo; bb < bhi; bb++) {
                const float r = rz[bb][in];
                const float z = rz[bb][Hs + in];
                const float n = tanh_(fmaf(r, hpn[bb], xc[bb]));
                const float hold = hsh[bb][in];
                const float hnew = fmaf(z, hold - n, n);
                hsh[bb][in] = hnew;
                out[((size_t)tt * Bs + b0 + bb) * (2 * Hs) + dir * Hs + in] = hnew;
            }
        }
        __syncthreads();

        #pragma unroll
        for (int bb = 0; bb < NB; bb++) xc[bb] = xn[bb];
        tt = tn;
    }
}

// ---------------------------------------------------------------------------
extern "C" void kernel_launch(void* const* d_in, const int* in_sizes, int n_in,
                              void* d_out, int out_size)
{
    const float* x      = (const float*)d_in[0];
    const float* w_ih_f = (const float*)d_in[1];
    const float* w_hh_f = (const float*)d_in[2];
    const float* b_ih_f = (const float*)d_in[3];
    const float* b_hh_f = (const float*)d_in[4];
    const float* w_ih_b = (const float*)d_in[5];
    const float* w_hh_b = (const float*)d_in[6];
    const float* b_ih_b = (const float*)d_in[7];
    const float* b_hh_b = (const float*)d_in[8];
    float* out = (float*)d_out;

    const int proj_smem = (128 * Is + 96 * Is) * sizeof(float);   // 89600 B

    static bool attr_done = false;
    if (!attr_done) {
        cudaFuncSetAttribute(proj_kernel,
                             cudaFuncAttributeMaxDynamicSharedMemorySize, proj_smem);
        attr_done = true;
    }

    dim3 pg(6, Ms / 128);     // gtile*dir fastest -> L2 reuse of x tiles
    proj_kernel<<<pg, 512, proj_smem>>>(x, w_ih_f, b_ih_f, w_ih_b, b_ih_b);
    scan_kernel<<<148, 576>>>(w_hh_f, b_hh_f, w_hh_b, b_hh_b, out);
}

// round 9
// speedup vs baseline: 1.1695x; 1.1695x over previous
#include <cuda_runtime.h>
#include <cstdint>

#define Hs 96
#define Is 100
#define Ts 512
#define Bs 512
#define Gs 288               // 3*H
#define Ms (Ts*Bs)           // 262144 rows
#define NB 7                 // batches per scan CTA

// Scratch for input projections: [dir][m][g]
__device__ float g_xproj[2][(size_t)Ms * Gs];

typedef unsigned long long u64;

__device__ __forceinline__ u64 fma2(u64 a, u64 b, u64 c) {
    u64 d;
    asm("fma.rn.f32x2 %0, %1, %2, %3;" : "=l"(d) : "l"(a), "l"(b), "l"(c));
    return d;
}
__device__ __forceinline__ float hsum2(u64 a) {
    float x, y;
    asm("mov.b64 {%0,%1}, %2;" : "=f"(x), "=f"(y) : "l"(a));
    return x + y;
}
__device__ __forceinline__ float sigm(float x) {
    return __fdividef(1.0f, 1.0f + __expf(-x));
}
__device__ __forceinline__ float tanh_(float x) {
    return 1.0f - __fdividef(2.0f, 1.0f + __expf(2.0f * x));
}

// ---------------------------------------------------------------------------
// Input projection. Tile 128 m-rows x 96 g-cols, K=100. 512 threads,
// thread tile 8x3. grid=(6, 2048): blockIdx.x = gtile + 3*dir fastest so the
// 6 CTAs sharing an x-tile are schedule-adjacent (x from L2).
// ---------------------------------------------------------------------------
__global__ __launch_bounds__(512, 1) void proj_kernel(
    const float* __restrict__ x,
    const float* __restrict__ wf, const float* __restrict__ bf,
    const float* __restrict__ wb, const float* __restrict__ bb)
{
    extern __shared__ float psm[];
    float* xs = psm;                  // [128][100]
    float* ws = psm + 128 * Is;       // [96][100]

    const int bx = blockIdx.x;
    const int dir = (bx >= 3);
    const int g0 = (dir ? bx - 3 : bx) * 96;
    const size_t m0 = (size_t)blockIdx.y * 128;
    const int tid = threadIdx.x;

    const float* __restrict__ w    = dir ? wb : wf;
    const float* __restrict__ bias = dir ? bb : bf;

    {
        const float4* xsrc = (const float4*)(x + m0 * Is);
        float4* xd = (float4*)xs;
        for (int i = tid; i < 128 * Is / 4; i += 512) xd[i] = xsrc[i];
        const float4* wsrc = (const float4*)(w + (size_t)g0 * Is);
        float4* wd = (float4*)ws;
        for (int i = tid; i < 96 * Is / 4; i += 512) wd[i] = wsrc[i];
    }
    __syncthreads();

    const int cg = tid & 31;   // col group
    const int rg = tid >> 5;   // row group

    u64 acc[8][3];
    #pragma unroll
    for (int r = 0; r < 8; r++)
        #pragma unroll
        for (int c = 0; c < 3; c++) acc[r][c] = 0ull;

    #pragma unroll 5
    for (int k4 = 0; k4 < 25; k4++) {
        ulonglong2 wv[3];
        #pragma unroll
        for (int c = 0; c < 3; c++)
            wv[c] = *(const ulonglong2*)&ws[(cg + 32 * c) * Is + 4 * k4];
        #pragma unroll
        for (int r = 0; r < 8; r++) {
            const ulonglong2 xv = *(const ulonglong2*)&xs[(rg * 8 + r) * Is + 4 * k4];
            #pragma unroll
            for (int c = 0; c < 3; c++) {
                acc[r][c] = fma2(xv.x, wv[c].x, acc[r][c]);
                acc[r][c] = fma2(xv.y, wv[c].y, acc[r][c]);
            }
        }
    }

    #pragma unroll
    for (int c = 0; c < 3; c++) {
        const int gcol = g0 + cg + 32 * c;
        const float bv = __ldg(&bias[gcol]);
        #pragma unroll
        for (int r = 0; r < 8; r++) {
            const size_t m = m0 + rg * 8 + r;
            g_xproj[dir][m * Gs + gcol] = hsum2(acc[r][c]) + bv;
        }
    }
}

// ---------------------------------------------------------------------------
// Recurrent scan. 148 CTAs (74 overlapping batch-groups of 7 x 2 dirs),
// 384 threads = 12 warps (3/3/3/3 per SMSP, balanced).
// Thread layout: 4 lanes per hidden index il = tid>>2:
//   role = tid&3:  0 -> r-row (g=il), 1 -> z-row (g=96+il),
//                  2 -> n-row (g=192+il), 3 -> n-dup (spare, no stores).
// Each thread holds its W_hh row in 48 u64 registers; h broadcast from smem
// with warp-UNIFORM addresses. Epilogue is branch-free and warp-local:
// every lane computes sigm() of its own pre-activation, two shfls pull r and
// z into the n lanes, n lanes do tanh + state update with h_old kept in
// registers. ONE __syncthreads per step (publish h into double buffer).
// ---------------------------------------------------------------------------
__global__ __launch_bounds__(384, 1) void scan_kernel(
    const float* __restrict__ whf, const float* __restrict__ bhf,
    const float* __restrict__ whb, const float* __restrict__ bhb,
    float* __restrict__ out)
{
    __shared__ __align__(16) float hsh[2][NB][Hs];   // double-buffered hidden state

    const int tid  = threadIdx.x;
    const int lane = tid & 31;
    const int il   = tid >> 2;                   // hidden index 0..95
    const int role = tid & 3;                    // 0 r, 1 z, 2 n, 3 spare
    const int g    = (role == 0) ? il : (role == 1) ? (Hs + il) : (2 * Hs + il);
    const bool is_n = (role == 2);

    const int dir = blockIdx.x & 1;
    const int gi  = blockIdx.x >> 1;             // 0..73
    int b0 = 7 * gi; if (b0 > Bs - NB) b0 = Bs - NB;   // overlap-pad last group

    const float* __restrict__ wh = dir ? whb : whf;
    const float* __restrict__ bh = dir ? bhb : bhf;

    // W_hh row g -> 48 u64 registers
    u64 w2[48];
    {
        const u64* wrow = (const u64*)(wh + g * Hs);
        #pragma unroll
        for (int j = 0; j < 48; j++) w2[j] = __ldg(&wrow[j]);
    }
    const float bhv = __ldg(&bh[g]);

    for (int i = tid; i < 2 * NB * Hs; i += 384) (&hsh[0][0][0])[i] = 0.0f;

    const float* __restrict__ xpb = g_xproj[dir];
    const int t_first = dir ? (Ts - 1) : 0;
    const int tstep   = dir ? -1 : 1;

    float xc[NB], xn[NB], hreg[NB];
    #pragma unroll
    for (int bb = 0; bb < NB; bb++) {
        hreg[bb] = 0.0f;
        xc[bb] = __ldg(&xpb[((size_t)t_first * Bs + b0 + bb) * Gs + g]);
    }

    __syncthreads();

    int tt = t_first;
    int p = 0;
    #pragma unroll 1
    for (int t = 0; t < Ts; t++) {
        // Prefetch next step's xp
        const int tn = (t == Ts - 1) ? tt : (tt + tstep);
        #pragma unroll
        for (int bb = 0; bb < NB; bb++)
            xn[bb] = __ldg(&xpb[((size_t)tn * Bs + b0 + bb) * Gs + g]);

        // Matvec: dot[bb] = W_hh[g,:] . h[bb]  (uniform broadcast h loads)
        u64 acc[NB];
        #pragma unroll
        for (int bb = 0; bb < NB; bb++) acc[bb] = 0ull;
        #pragma unroll
        for (int j = 0; j < 24; j++) {
            ulonglong2 hv[NB];
            #pragma unroll
            for (int bb = 0; bb < NB; bb++)
                hv[bb] = *(const ulonglong2*)&hsh[p][bb][4 * j];
            #pragma unroll
            for (int bb = 0; bb < NB; bb++) {
                acc[bb] = fma2(w2[2 * j],     hv[bb].x, acc[bb]);
                acc[bb] = fma2(w2[2 * j + 1], hv[bb].y, acc[bb]);
            }
        }

        // Branch-free warp-local epilogue
        const int srcR = lane & ~3;              // role-0 lane of this il group
        #pragma unroll
        for (int bb = 0; bb < NB; bb++) {
            const float dot = hsum2(acc[bb]) + bhv;
            const float act = sigm(xc[bb] + dot);        // r/z lanes meaningful
            const float rv  = __shfl_sync(0xFFFFFFFFu, act, srcR);
            const float zv  = __shfl_sync(0xFFFFFFFFu, act, srcR | 1);
            const float nv  = tanh_(fmaf(rv, dot, xc[bb]));   // n lanes meaningful
            const float hnew = fmaf(zv, hreg[bb] - nv, nv);
            hreg[bb] = hnew;
            if (is_n) {
                hsh[1 - p][bb][il] = hnew;
                out[((size_t)tt * Bs + b0 + bb) * (2 * Hs) + dir * Hs + il] = hnew;
            }
        }
        __syncthreads();

        p ^= 1;
        #pragma unroll
        for (int bb = 0; bb < NB; bb++) xc[bb] = xn[bb];
        tt = tn;
    }
}

// ---------------------------------------------------------------------------
extern "C" void kernel_launch(void* const* d_in, const int* in_sizes, int n_in,
                              void* d_out, int out_size)
{
    const float* x      = (const float*)d_in[0];
    const float* w_ih_f = (const float*)d_in[1];
    const float* w_hh_f = (const float*)d_in[2];
    const float* b_ih_f = (const float*)d_in[3];
    const float* b_hh_f = (const float*)d_in[4];
    const float* w_ih_b = (const float*)d_in[5];
    const float* w_hh_b = (const float*)d_in[6];
    const float* b_ih_b = (const float*)d_in[7];
    const float* b_hh_b = (const float*)d_in[8];
    float* out = (float*)d_out;

    const int proj_smem = (128 * Is + 96 * Is) * sizeof(float);   // 89600 B

    static bool attr_done = false;
    if (!attr_done) {
        cudaFuncSetAttribute(proj_kernel,
                             cudaFuncAttributeMaxDynamicSharedMemorySize, proj_smem);
        attr_done = true;
    }

    dim3 pg(6, Ms / 128);     // gtile*dir fastest -> L2 reuse of x tiles
    proj_kernel<<<pg, 512, proj_smem>>>(x, w_ih_f, b_ih_f, w_ih_b, b_ih_b);
    scan_kernel<<<148, 384>>>(w_hh_f, b_hh_f, w_hh_b, b_hh_b, out);
}

// round 10
// speedup vs baseline: 1.2074x; 1.0325x over previous
#include <cuda_runtime.h>
#include <cstdint>

#define Hs 96
#define Is 100
#define Ts 512
#define Bs 512
#define Gs 288               // 3*H
#define Ms (Ts*Bs)           // 262144 rows
#define NB 7                 // batches per scan CTA
#define XP 104               // xs pitch (floats): 416B = 16B-aligned rows

// Scratch for input projections: [dir][m][g]
__device__ float g_xproj[2][(size_t)Ms * Gs];

typedef unsigned long long u64;

__device__ __forceinline__ u64 fma2(u64 a, u64 b, u64 c) {
    u64 d;
    asm("fma.rn.f32x2 %0, %1, %2, %3;" : "=l"(d) : "l"(a), "l"(b), "l"(c));
    return d;
}
__device__ __forceinline__ float hsum2(u64 a) {
    float x, y;
    asm("mov.b64 {%0,%1}, %2;" : "=f"(x), "=f"(y) : "l"(a));
    return x + y;
}
__device__ __forceinline__ float sigm(float x) {
    return __fdividef(1.0f, 1.0f + __expf(-x));
}
__device__ __forceinline__ float tanh_(float x) {
    return 1.0f - __fdividef(2.0f, 1.0f + __expf(2.0f * x));
}

// ---------------------------------------------------------------------------
// Input projection. Tile 128 m-rows x 96 g-cols, K=100. 512 threads,
// thread tile 8x3.
// W tile stored k-pair-TRANSPOSED: wst[k2][g] = (W[g][2k2], W[g][2k2+1]) u64.
//   -> wv loads are lane-consecutive u64 = conflict-free spread (2 wf).
//   (Old layout had 400B lane stride -> 4-way bank conflict on every load.)
// x tile row-major with pitch 104 floats so xv LDS.128 is 16B-aligned+uniform.
// grid=(6, 2048): blockIdx.x = gtile + 3*dir fastest -> L2 reuse of x tiles.
// ---------------------------------------------------------------------------
__global__ __launch_bounds__(512, 1) void proj_kernel(
    const float* __restrict__ x,
    const float* __restrict__ wf, const float* __restrict__ bf,
    const float* __restrict__ wb, const float* __restrict__ bb)
{
    extern __shared__ __align__(16) float psm[];
    float* xs  = psm;                          // [128][XP]
    u64*   wst = (u64*)(psm + 128 * XP);       // [50][96]

    const int bx = blockIdx.x;
    const int dir = (bx >= 3);
    const int g0 = (dir ? bx - 3 : bx) * 96;
    const size_t m0 = (size_t)blockIdx.y * 128;
    const int tid = threadIdx.x;

    const float* __restrict__ w    = dir ? wb : wf;
    const float* __restrict__ bias = dir ? bb : bf;

    // x tile: copy 128 rows of 100 floats (25 float4) into pitch-26-float4 rows
    {
        const float4* xsrc = (const float4*)(x + m0 * Is);
        float4* xd = (float4*)xs;
        for (int i = tid; i < 128 * 25; i += 512) {
            const int row = i / 25, c4 = i - row * 25;
            xd[row * (XP / 4) + c4] = xsrc[i];
        }
    }
    // W tile: transposed-paired. i = g*50 + k2 -> coalesced u64 gmem reads.
    {
        for (int i = tid; i < 96 * 50; i += 512) {
            const int g = i / 50, k2 = i - g * 50;
            const u64 v = __ldg((const u64*)(w + (size_t)(g0 + g) * Is) + k2);
            wst[k2 * 96 + g] = v;
        }
    }
    __syncthreads();

    const int cg = tid & 31;   // col group: cols cg + 32*c
    const int rg = tid >> 5;   // row group: rows rg*8 + r

    u64 acc[8][3];
    #pragma unroll
    for (int r = 0; r < 8; r++)
        #pragma unroll
        for (int c = 0; c < 3; c++) acc[r][c] = 0ull;

    #pragma unroll 5
    for (int k4 = 0; k4 < 25; k4++) {          // 4 k-values per iter
        u64 wv0[3], wv1[3];
        #pragma unroll
        for (int c = 0; c < 3; c++) {
            wv0[c] = wst[(2 * k4)     * 96 + cg + 32 * c];
            wv1[c] = wst[(2 * k4 + 1) * 96 + cg + 32 * c];
        }
        #pragma unroll
        for (int r = 0; r < 8; r++) {
            const ulonglong2 xv = *(const ulonglong2*)&xs[(rg * 8 + r) * XP + 4 * k4];
            #pragma unroll
            for (int c = 0; c < 3; c++) {
                acc[r][c] = fma2(xv.x, wv0[c], acc[r][c]);
                acc[r][c] = fma2(xv.y, wv1[c], acc[r][c]);
            }
        }
    }

    #pragma unroll
    for (int c = 0; c < 3; c++) {
        const int gcol = g0 + cg + 32 * c;
        const float bv = __ldg(&bias[gcol]);
        #pragma unroll
        for (int r = 0; r < 8; r++) {
            const size_t m = m0 + rg * 8 + r;
            g_xproj[dir][m * Gs + gcol] = hsum2(acc[r][c]) + bv;
        }
    }
}

// ---------------------------------------------------------------------------
// Recurrent scan. 148 CTAs (74 overlapping batch-groups of 7 x 2 dirs),
// 288 threads = 9 warps (MINIMUM wavefront count: L1 wavefronts are the
// SM-serial binding resource; wf = warps x h-bytes/8, so fewer warps win
// even with SMSP imbalance). Thread g owns W_hh row g in 48 u64 registers;
// h read warp-UNIFORM from smem.
// Epilogue: stage2 r/z threads apply their own sigmoid and publish the
// activated scalar; n threads publish (dot_n, xp_n) as float2. Stage3 spread
// over ALL 288 threads (2-3 elems each via bb += 3).
// ---------------------------------------------------------------------------
__global__ __launch_bounds__(288, 1) void scan_kernel(
    const float* __restrict__ whf, const float* __restrict__ bhf,
    const float* __restrict__ whb, const float* __restrict__ bhb,
    float* __restrict__ out)
{
    __shared__ __align__(16) float hsh[NB][Hs];    // hidden state
    __shared__ float  rz[NB][2 * Hs];              // sigmoided r [0,96), z [96,192)
    __shared__ float2 dxn[NB][Hs];                 // (dot_n, xp_n)

    const int tid = threadIdx.x;                   // gate row g
    const int dir = blockIdx.x & 1;
    const int gi  = blockIdx.x >> 1;               // 0..73
    int b0 = 7 * gi; if (b0 > Bs - NB) b0 = Bs - NB;   // overlap-pad last group

    const float* __restrict__ wh = dir ? whb : whf;
    const float* __restrict__ bh = dir ? bhb : bhf;

    // W_hh row -> registers
    u64 w2[48];
    {
        const u64* wrow = (const u64*)(wh + tid * Hs);
        #pragma unroll
        for (int j = 0; j < 48; j++) w2[j] = __ldg(&wrow[j]);
    }
    const float bhv = __ldg(&bh[tid]);

    for (int i = tid; i < NB * Hs; i += 288) (&hsh[0][0])[i] = 0.0f;

    const float* __restrict__ xpb = g_xproj[dir];
    const int t_first = dir ? (Ts - 1) : 0;
    const int tstep   = dir ? -1 : 1;

    const bool is_n = (tid >= 2 * Hs);
    const int  gn   = tid - 2 * Hs;                // n-row index (valid if is_n)

    // stage3 mapping: thread handles (bb0, i0), (bb0+3, i0), (bb0+6, i0 if bb0==0)
    const int bb0 = (tid < Hs) ? 0 : (tid < 2 * Hs ? 1 : 2);
    const int i0  = tid - bb0 * Hs;

    float xc[NB], xn[NB];
    #pragma unroll
    for (int bbq = 0; bbq < NB; bbq++)
        xc[bbq] = __ldg(&xpb[((size_t)t_first * Bs + b0 + bbq) * Gs + tid]);

    __syncthreads();

    int tt = t_first;
    #pragma unroll 1
    for (int t = 0; t < Ts; t++) {
        // Prefetch next step's xp (consumed next iteration)
        const int tn = (t == Ts - 1) ? tt : (tt + tstep);
        #pragma unroll
        for (int bbq = 0; bbq < NB; bbq++)
            xn[bbq] = __ldg(&xpb[((size_t)tn * Bs + b0 + bbq) * Gs + tid]);

        // Stage 1: matvec, NB independent fma2 chains, uniform h broadcasts
        u64 acc[NB];
        #pragma unroll
        for (int bbq = 0; bbq < NB; bbq++) acc[bbq] = 0ull;
        #pragma unroll
        for (int j = 0; j < 24; j++) {
            ulonglong2 hv[NB];
            #pragma unroll
            for (int bbq = 0; bbq < NB; bbq++)
                hv[bbq] = *(const ulonglong2*)&hsh[bbq][4 * j];
            #pragma unroll
            for (int bbq = 0; bbq < NB; bbq++) {
                acc[bbq] = fma2(w2[2 * j],     hv[bbq].x, acc[bbq]);
                acc[bbq] = fma2(w2[2 * j + 1], hv[bbq].y, acc[bbq]);
            }
        }

        // Stage 2: publish. r/z rows apply sigmoid themselves.
        if (!is_n) {
            #pragma unroll
            for (int bbq = 0; bbq < NB; bbq++)
                rz[bbq][tid] = sigm(xc[bbq] + hsum2(acc[bbq]) + bhv);
        } else {
            #pragma unroll
            for (int bbq = 0; bbq < NB; bbq++)
                dxn[bbq][gn] = make_float2(hsum2(acc[bbq]) + bhv, xc[bbq]);
        }
        __syncthreads();

        // Stage 3: spread over all 288 threads
        for (int bbq = bb0; bbq < NB; bbq += 3) {
            const float r = rz[bbq][i0];
            const float z = rz[bbq][Hs + i0];
            const float2 v = dxn[bbq][i0];
            const float n = tanh_(fmaf(r, v.x, v.y));
            const float hold = hsh[bbq][i0];
            const float hnew = fmaf(z, hold - n, n);
            hsh[bbq][i0] = hnew;
            out[((size_t)tt * Bs + b0 + bbq) * (2 * Hs) + dir * Hs + i0] = hnew;
        }
        __syncthreads();

        #pragma unroll
        for (int bbq = 0; bbq < NB; bbq++) xc[bbq] = xn[bbq];
        tt = tn;
    }
}

// ---------------------------------------------------------------------------
extern "C" void kernel_launch(void* const* d_in, const int* in_sizes, int n_in,
                              void* d_out, int out_size)
{
    const float* x      = (const float*)d_in[0];
    const float* w_ih_f = (const float*)d_in[1];
    const float* w_hh_f = (const float*)d_in[2];
    const float* b_ih_f = (const float*)d_in[3];
    const float* b_hh_f = (const float*)d_in[4];
    const float* w_ih_b = (const float*)d_in[5];
    const float* w_hh_b = (const float*)d_in[6];
    const float* b_ih_b = (const float*)d_in[7];
    const float* b_hh_b = (const float*)d_in[8];
    float* out = (float*)d_out;

    const int proj_smem = 128 * XP * sizeof(float) + 50 * 96 * sizeof(u64); // 91648 B

    static bool attr_done = false;
    if (!attr_done) {
        cudaFuncSetAttribute(proj_kernel,
                             cudaFuncAttributeMaxDynamicSharedMemorySize, proj_smem);
        attr_done = true;
    }

    dim3 pg(6, Ms / 128);     // gtile+dir fastest -> L2 reuse of x tiles
    proj_kernel<<<pg, 512, proj_smem>>>(x, w_ih_f, b_ih_f, w_ih_b, b_ih_b);
    scan_kernel<<<148, 288>>>(w_hh_f, b_hh_f, w_hh_b, b_hh_b, out);
}

// round 11
// speedup vs baseline: 1.4107x; 1.1683x over previous
#include <cuda_runtime.h>
#include <cstdint>

#define Hs 96
#define Is 100
#define Ts 512
#define Bs 512
#define Gs 288               // 3*H
#define Ms (Ts*Bs)           // 262144 rows
#define NB 7                 // batches per scan CTA
#define TM 64                // proj tile rows
#define NMT (Ms / TM)        // 4096 m-tiles

// Scratch for input projections: [dir][m][g]
__device__ float g_xproj[2][(size_t)Ms * Gs];

typedef unsigned long long u64;

__device__ __forceinline__ u64 fma2(u64 a, u64 b, u64 c) {
    u64 d;
    asm("fma.rn.f32x2 %0, %1, %2, %3;" : "=l"(d) : "l"(a), "l"(b), "l"(c));
    return d;
}
__device__ __forceinline__ float hsum2(u64 a) {
    float x, y;
    asm("mov.b64 {%0,%1}, %2;" : "=f"(x), "=f"(y) : "l"(a));
    return x + y;
}
__device__ __forceinline__ float sigm(float x) {
    return __fdividef(1.0f, 1.0f + __expf(-x));
}
__device__ __forceinline__ float tanh_(float x) {
    return 1.0f - __fdividef(2.0f, 1.0f + __expf(2.0f * x));
}

// ---------------------------------------------------------------------------
// Input projection — PERSISTENT + double-buffered.
// grid (6, 48): bx -> (dir, 96-col group); each CTA loops m-tiles stride 48.
// 256 threads, 2 CTAs/SM. W tile loaded ONCE per CTA (transposed-paired:
// wst[k2][g], lane-consecutive u64 reads, dedup -> 1 wf). Next x tile is
// prefetched into registers during the FMA loop and committed to smem after.
// Thread tile 4 rows x 6 cols (acc = 24 u64).
// ---------------------------------------------------------------------------
__global__ __launch_bounds__(256, 2) void proj_kernel(
    const float* __restrict__ x,
    const float* __restrict__ wf, const float* __restrict__ bf,
    const float* __restrict__ wb, const float* __restrict__ bb)
{
    extern __shared__ __align__(16) float psm[];
    float* xs  = psm;                          // [TM][100]
    u64*   wst = (u64*)(psm + TM * Is);        // [50][96]

    const int bx  = blockIdx.x;                // 0..5
    const int dir = (bx >= 3);
    const int g0  = (dir ? bx - 3 : bx) * 96;
    const int tid = threadIdx.x;

    const float* __restrict__ w    = dir ? wb : wf;
    const float* __restrict__ bias = dir ? bb : bf;

    // W tile, once: wst[k2*96+g] = (W[g0+g][2k2], W[g0+g][2k2+1])
    for (int i = tid; i < 50 * 96; i += 256) {
        const int k2 = i / 96, g = i - k2 * 96;
        wst[i] = *(const u64*)(w + (size_t)(g0 + g) * Is + 2 * k2);
    }

    // First x tile (64 rows x 100 floats = 1600 float4, contiguous)
    int mt = blockIdx.y;
    {
        const float4* src = (const float4*)(x + (size_t)mt * TM * Is);
        float4* dst = (float4*)xs;
        for (int i = tid; i < TM * Is / 4; i += 256) dst[i] = src[i];
    }

    const int cg = tid & 15;     // col group: cols g0 + cg + 16*c, c<6
    const int rg = tid >> 4;     // row group: rows rg*4 + r, rg<16

    float bv[6];
    #pragma unroll
    for (int c = 0; c < 6; c++) bv[c] = __ldg(&bias[g0 + cg + 16 * c]);

    __syncthreads();

    while (true) {
        const int mtn = mt + gridDim.y;
        const bool has_next = (mtn < NMT);

        // Prefetch next tile into registers (latency hidden by FMA loop)
        float4 pf[7];
        if (has_next) {
            const float4* src = (const float4*)(x + (size_t)mtn * TM * Is);
            #pragma unroll
            for (int j = 0; j < 7; j++) {
                const int idx = tid + j * 256;
                if (idx < TM * Is / 4) pf[j] = __ldg(&src[idx]);
            }
        }

        // Compute: 25 k4-iters, 48 fma2 each
        u64 acc[4][6];
        #pragma unroll
        for (int r = 0; r < 4; r++)
            #pragma unroll
            for (int c = 0; c < 6; c++) acc[r][c] = 0ull;

        #pragma unroll 5
        for (int k4 = 0; k4 < 25; k4++) {
            u64 wv0[6], wv1[6];
            #pragma unroll
            for (int c = 0; c < 6; c++) {
                wv0[c] = wst[(2 * k4)     * 96 + cg + 16 * c];
                wv1[c] = wst[(2 * k4 + 1) * 96 + cg + 16 * c];
            }
            #pragma unroll
            for (int r = 0; r < 4; r++) {
                const ulonglong2 xv = *(const ulonglong2*)&xs[(rg * 4 + r) * Is + 4 * k4];
                #pragma unroll
                for (int c = 0; c < 6; c++) {
                    acc[r][c] = fma2(xv.x, wv0[c], acc[r][c]);
                    acc[r][c] = fma2(xv.y, wv1[c], acc[r][c]);
                }
            }
        }

        // Store tile outputs
        const size_t m0 = (size_t)mt * TM;
        #pragma unroll
        for (int c = 0; c < 6; c++) {
            const int gcol = g0 + cg + 16 * c;
            #pragma unroll
            for (int r = 0; r < 4; r++)
                g_xproj[dir][(m0 + rg * 4 + r) * Gs + gcol] = hsum2(acc[r][c]) + bv[c];
        }

        if (!has_next) break;
        __syncthreads();                       // everyone done reading xs
        {
            float4* dst = (float4*)xs;
            #pragma unroll
            for (int j = 0; j < 7; j++) {
                const int idx = tid + j * 256;
                if (idx < TM * Is / 4) dst[idx] = pf[j];
            }
        }
        __syncthreads();                       // new tile visible
        mt = mtn;
    }
}

// ---------------------------------------------------------------------------
// Recurrent scan (unchanged from R10 best). 148 CTAs (74 overlapping
// batch-groups of 7 x 2 dirs), 288 threads = 9 warps (minimum-wavefront
// design). Thread g owns W_hh row g in 48 u64 registers; h read warp-UNIFORM.
// ---------------------------------------------------------------------------
__global__ __launch_bounds__(288, 1) void scan_kernel(
    const float* __restrict__ whf, const float* __restrict__ bhf,
    const float* __restrict__ whb, const float* __restrict__ bhb,
    float* __restrict__ out)
{
    __shared__ __align__(16) float hsh[NB][Hs];    // hidden state
    __shared__ float  rz[NB][2 * Hs];              // sigmoided r [0,96), z [96,192)
    __shared__ float2 dxn[NB][Hs];                 // (dot_n, xp_n)

    const int tid = threadIdx.x;                   // gate row g
    const int dir = blockIdx.x & 1;
    const int gi  = blockIdx.x >> 1;               // 0..73
    int b0 = 7 * gi; if (b0 > Bs - NB) b0 = Bs - NB;   // overlap-pad last group

    const float* __restrict__ wh = dir ? whb : whf;
    const float* __restrict__ bh = dir ? bhb : bhf;

    u64 w2[48];
    {
        const u64* wrow = (const u64*)(wh + tid * Hs);
        #pragma unroll
        for (int j = 0; j < 48; j++) w2[j] = __ldg(&wrow[j]);
    }
    const float bhv = __ldg(&bh[tid]);

    for (int i = tid; i < NB * Hs; i += 288) (&hsh[0][0])[i] = 0.0f;

    const float* __restrict__ xpb = g_xproj[dir];
    const int t_first = dir ? (Ts - 1) : 0;
    const int tstep   = dir ? -1 : 1;

    const bool is_n = (tid >= 2 * Hs);
    const int  gn   = tid - 2 * Hs;

    const int bb0 = (tid < Hs) ? 0 : (tid < 2 * Hs ? 1 : 2);
    const int i0  = tid - bb0 * Hs;

    float xc[NB], xn[NB];
    #pragma unroll
    for (int bbq = 0; bbq < NB; bbq++)
        xc[bbq] = __ldg(&xpb[((size_t)t_first * Bs + b0 + bbq) * Gs + tid]);

    __syncthreads();

    int tt = t_first;
    #pragma unroll 1
    for (int t = 0; t < Ts; t++) {
        const int tn = (t == Ts - 1) ? tt : (tt + tstep);
        #pragma unroll
        for (int bbq = 0; bbq < NB; bbq++)
            xn[bbq] = __ldg(&xpb[((size_t)tn * Bs + b0 + bbq) * Gs + tid]);

        u64 acc[NB];
        #pragma unroll
        for (int bbq = 0; bbq < NB; bbq++) acc[bbq] = 0ull;
        #pragma unroll
        for (int j = 0; j < 24; j++) {
            ulonglong2 hv[NB];
            #pragma unroll
            for (int bbq = 0; bbq < NB; bbq++)
                hv[bbq] = *(const ulonglong2*)&hsh[bbq][4 * j];
            #pragma unroll
            for (int bbq = 0; bbq < NB; bbq++) {
                acc[bbq] = fma2(w2[2 * j],     hv[bbq].x, acc[bbq]);
                acc[bbq] = fma2(w2[2 * j + 1], hv[bbq].y, acc[bbq]);
            }
        }

        if (!is_n) {
            #pragma unroll
            for (int bbq = 0; bbq < NB; bbq++)
                rz[bbq][tid] = sigm(xc[bbq] + hsum2(acc[bbq]) + bhv);
        } else {
            #pragma unroll
            for (int bbq = 0; bbq < NB; bbq++)
                dxn[bbq][gn] = make_float2(hsum2(acc[bbq]) + bhv, xc[bbq]);
        }
        __syncthreads();

        for (int bbq = bb0; bbq < NB; bbq += 3) {
            const float r = rz[bbq][i0];
            const float z = rz[bbq][Hs + i0];
            const float2 v = dxn[bbq][i0];
            const float n = tanh_(fmaf(r, v.x, v.y));
            const float hold = hsh[bbq][i0];
            const float hnew = fmaf(z, hold - n, n);
            hsh[bbq][i0] = hnew;
            out[((size_t)tt * Bs + b0 + bbq) * (2 * Hs) + dir * Hs + i0] = hnew;
        }
        __syncthreads();

        #pragma unroll
        for (int bbq = 0; bbq < NB; bbq++) xc[bbq] = xn[bbq];
        tt = tn;
    }
}

// ---------------------------------------------------------------------------
extern "C" void kernel_launch(void* const* d_in, const int* in_sizes, int n_in,
                              void* d_out, int out_size)
{
    const float* x      = (const float*)d_in[0];
    const float* w_ih_f = (const float*)d_in[1];
    const float* w_hh_f = (const float*)d_in[2];
    const float* b_ih_f = (const float*)d_in[3];
    const float* b_hh_f = (const float*)d_in[4];
    const float* w_ih_b = (const float*)d_in[5];
    const float* w_hh_b = (const float*)d_in[6];
    const float* b_ih_b = (const float*)d_in[7];
    const float* b_hh_b = (const float*)d_in[8];
    float* out = (float*)d_out;

    const int proj_smem = TM * Is * sizeof(float) + 50 * 96 * sizeof(u64); // 64000 B

    static bool attr_done = false;
    if (!attr_done) {
        cudaFuncSetAttribute(proj_kernel,
                             cudaFuncAttributeMaxDynamicSharedMemorySize, proj_smem);
        attr_done = true;
    }

    dim3 pg(6, 48);           // persistent CTAs, ~2/SM
    proj_kernel<<<pg, 256, proj_smem>>>(x, w_ih_f, b_ih_f, w_ih_b, b_ih_b);
    scan_kernel<<<148, 288>>>(w_hh_f, b_hh_f, w_hh_b, b_hh_b, out);
}

// round 12
// speedup vs baseline: 1.4458x; 1.0249x over previous
#include <cuda_runtime.h>
#include <cstdint>

#define Hs 96
#define Is 100
#define Ts 512
#define Bs 512
#define Gs 288               // 3*H
#define Ms (Ts*Bs)           // 262144 rows
#define NB 7                 // batches per scan CTA
#define TM 64                // proj tile rows
#define NMT (Ms / TM)        // 4096 m-tiles

// Scratch for input projections: [dir][m][g]
__device__ float g_xproj[2][(size_t)Ms * Gs];

typedef unsigned long long u64;

__device__ __forceinline__ u64 fma2(u64 a, u64 b, u64 c) {
    u64 d;
    asm("fma.rn.f32x2 %0, %1, %2, %3;" : "=l"(d) : "l"(a), "l"(b), "l"(c));
    return d;
}
__device__ __forceinline__ float hsum2(u64 a) {
    float x, y;
    asm("mov.b64 {%0,%1}, %2;" : "=f"(x), "=f"(y) : "l"(a));
    return x + y;
}
__device__ __forceinline__ float sigm(float x) {
    return __fdividef(1.0f, 1.0f + __expf(-x));
}
__device__ __forceinline__ float tanh_(float x) {
    return 1.0f - __fdividef(2.0f, 1.0f + __expf(2.0f * x));
}

// ---------------------------------------------------------------------------
// Input projection — PERSISTENT + double-buffered prefetch + coalesced stores.
// grid (6, 49): bx -> (dir, 96-col group); each CTA loops m-tiles stride 49.
// 256 threads, 2 CTAs/SM. W tile loaded ONCE per CTA (transposed-paired
// wst[k2][g]: lane-consecutive u64 reads -> 2-wf spread, reused over 8 rows).
// Thread tile 8 rows x 3 cols with cg = tid&31: warp lanes cover 32
// consecutive g-columns -> ALL output stores are full-warp 128B coalesced.
// Next x tile prefetched into registers during the FMA loop.
// ---------------------------------------------------------------------------
__global__ __launch_bounds__(256, 2) void proj_kernel(
    const float* __restrict__ x,
    const float* __restrict__ wf, const float* __restrict__ bf,
    const float* __restrict__ wb, const float* __restrict__ bb)
{
    extern __shared__ __align__(16) float psm[];
    float* xs  = psm;                          // [TM][100]
    u64*   wst = (u64*)(psm + TM * Is);        // [50][96]

    const int bx  = blockIdx.x;                // 0..5
    const int dir = (bx >= 3);
    const int g0  = (dir ? bx - 3 : bx) * 96;
    const int tid = threadIdx.x;

    const float* __restrict__ w    = dir ? wb : wf;
    const float* __restrict__ bias = dir ? bb : bf;

    // W tile, once: wst[k2*96+g] = (W[g0+g][2k2], W[g0+g][2k2+1])
    for (int i = tid; i < 96 * 50; i += 256) {
        const int g = i / 50, k2 = i - g * 50;
        wst[k2 * 96 + g] = *(const u64*)(w + (size_t)(g0 + g) * Is + 2 * k2);
    }

    // First x tile (64 rows x 100 floats = 1600 float4, contiguous)
    int mt = blockIdx.y;
    {
        const float4* src = (const float4*)(x + (size_t)mt * TM * Is);
        float4* dst = (float4*)xs;
        for (int i = tid; i < TM * Is / 4; i += 256) dst[i] = src[i];
    }

    const int cg = tid & 31;     // col: g0 + cg + 32*c, c<3 (warp = 32 consec cols)
    const int rg = tid >> 5;     // row group: rows rg*8 + r, r<8

    float bv[3];
    #pragma unroll
    for (int c = 0; c < 3; c++) bv[c] = __ldg(&bias[g0 + cg + 32 * c]);

    __syncthreads();

    while (true) {
        const int mtn = mt + gridDim.y;
        const bool has_next = (mtn < NMT);

        // Prefetch next tile into registers (latency hidden by FMA loop)
        float4 pf[7];
        if (has_next) {
            const float4* src = (const float4*)(x + (size_t)mtn * TM * Is);
            #pragma unroll
            for (int j = 0; j < 7; j++) {
                const int idx = tid + j * 256;
                if (idx < TM * Is / 4) pf[j] = __ldg(&src[idx]);
            }
        }

        // Compute: 25 k4-iters, 48 fma2 each
        u64 acc[8][3];
        #pragma unroll
        for (int r = 0; r < 8; r++)
            #pragma unroll
            for (int c = 0; c < 3; c++) acc[r][c] = 0ull;

        #pragma unroll 5
        for (int k4 = 0; k4 < 25; k4++) {
            u64 wv0[3], wv1[3];
            #pragma unroll
            for (int c = 0; c < 3; c++) {
                wv0[c] = wst[(2 * k4)     * 96 + cg + 32 * c];
                wv1[c] = wst[(2 * k4 + 1) * 96 + cg + 32 * c];
            }
            #pragma unroll
            for (int r = 0; r < 8; r++) {
                const ulonglong2 xv = *(const ulonglong2*)&xs[(rg * 8 + r) * Is + 4 * k4];
                #pragma unroll
                for (int c = 0; c < 3; c++) {
                    acc[r][c] = fma2(xv.x, wv0[c], acc[r][c]);
                    acc[r][c] = fma2(xv.y, wv1[c], acc[r][c]);
                }
            }
        }

        // Stores: warp lanes -> 32 consecutive g-cols = 128B coalesced STG
        const size_t m0 = (size_t)mt * TM;
        #pragma unroll
        for (int c = 0; c < 3; c++) {
            const int gcol = g0 + cg + 32 * c;
            #pragma unroll
            for (int r = 0; r < 8; r++)
                g_xproj[dir][(m0 + rg * 8 + r) * Gs + gcol] = hsum2(acc[r][c]) + bv[c];
        }

        if (!has_next) break;
        __syncthreads();                       // everyone done reading xs
        {
            float4* dst = (float4*)xs;
            #pragma unroll
            for (int j = 0; j < 7; j++) {
                const int idx = tid + j * 256;
                if (idx < TM * Is / 4) dst[idx] = pf[j];
            }
        }
        __syncthreads();                       // new tile visible
        mt = mtn;
    }
}

// ---------------------------------------------------------------------------
// Recurrent scan (unchanged — at structural floor for this design).
// 148 CTAs (74 overlapping batch-groups of 7 x 2 dirs), 288 threads = 9 warps
// (minimum-wavefront design). Thread g owns W_hh row g in 48 u64 registers;
// h read warp-UNIFORM from smem.
// ---------------------------------------------------------------------------
__global__ __launch_bounds__(288, 1) void scan_kernel(
    const float* __restrict__ whf, const float* __restrict__ bhf,
    const float* __restrict__ whb, const float* __restrict__ bhb,
    float* __restrict__ out)
{
    __shared__ __align__(16) float hsh[NB][Hs];    // hidden state
    __shared__ float  rz[NB][2 * Hs];              // sigmoided r [0,96), z [96,192)
    __shared__ float2 dxn[NB][Hs];                 // (dot_n, xp_n)

    const int tid = threadIdx.x;                   // gate row g
    const int dir = blockIdx.x & 1;
    const int gi  = blockIdx.x >> 1;               // 0..73
    int b0 = 7 * gi; if (b0 > Bs - NB) b0 = Bs - NB;   // overlap-pad last group

    const float* __restrict__ wh = dir ? whb : whf;
    const float* __restrict__ bh = dir ? bhb : bhf;

    u64 w2[48];
    {
        const u64* wrow = (const u64*)(wh + tid * Hs);
        #pragma unroll
        for (int j = 0; j < 48; j++) w2[j] = __ldg(&wrow[j]);
    }
    const float bhv = __ldg(&bh[tid]);

    for (int i = tid; i < NB * Hs; i += 288) (&hsh[0][0])[i] = 0.0f;

    const float* __restrict__ xpb = g_xproj[dir];
    const int t_first = dir ? (Ts - 1) : 0;
    const int tstep   = dir ? -1 : 1;

    const bool is_n = (tid >= 2 * Hs);
    const int  gn   = tid - 2 * Hs;

    const int bb0 = (tid < Hs) ? 0 : (tid < 2 * Hs ? 1 : 2);
    const int i0  = tid - bb0 * Hs;

    float xc[NB], xn[NB];
    #pragma unroll
    for (int bbq = 0; bbq < NB; bbq++)
        xc[bbq] = __ldg(&xpb[((size_t)t_first * Bs + b0 + bbq) * Gs + tid]);

    __syncthreads();

    int tt = t_first;
    #pragma unroll 1
    for (int t = 0; t < Ts; t++) {
        const int tn = (t == Ts - 1) ? tt : (tt + tstep);
        #pragma unroll
        for (int bbq = 0; bbq < NB; bbq++)
            xn[bbq] = __ldg(&xpb[((size_t)tn * Bs + b0 + bbq) * Gs + tid]);

        u64 acc[NB];
        #pragma unroll
        for (int bbq = 0; bbq < NB; bbq++) acc[bbq] = 0ull;
        #pragma unroll
        for (int j = 0; j < 24; j++) {
            ulonglong2 hv[NB];
            #pragma unroll
            for (int bbq = 0; bbq < NB; bbq++)
                hv[bbq] = *(const ulonglong2*)&hsh[bbq][4 * j];
            #pragma unroll
            for (int bbq = 0; bbq < NB; bbq++) {
                acc[bbq] = fma2(w2[2 * j],     hv[bbq].x, acc[bbq]);
                acc[bbq] = fma2(w2[2 * j + 1], hv[bbq].y, acc[bbq]);
            }
        }

        if (!is_n) {
            #pragma unroll
            for (int bbq = 0; bbq < NB; bbq++)
                rz[bbq][tid] = sigm(xc[bbq] + hsum2(acc[bbq]) + bhv);
        } else {
            #pragma unroll
            for (int bbq = 0; bbq < NB; bbq++)
                dxn[bbq][gn] = make_float2(hsum2(acc[bbq]) + bhv, xc[bbq]);
        }
        __syncthreads();

        for (int bbq = bb0; bbq < NB; bbq += 3) {
            const float r = rz[bbq][i0];
            const float z = rz[bbq][Hs + i0];
            const float2 v = dxn[bbq][i0];
            const float n = tanh_(fmaf(r, v.x, v.y));
            const float hold = hsh[bbq][i0];
            const float hnew = fmaf(z, hold - n, n);
            hsh[bbq][i0] = hnew;
            out[((size_t)tt * Bs + b0 + bbq) * (2 * Hs) + dir * Hs + i0] = hnew;
        }
        __syncthreads();

        #pragma unroll
        for (int bbq = 0; bbq < NB; bbq++) xc[bbq] = xn[bbq];
        tt = tn;
    }
}

// ---------------------------------------------------------------------------
extern "C" void kernel_launch(void* const* d_in, const int* in_sizes, int n_in,
                              void* d_out, int out_size)
{
    const float* x      = (const float*)d_in[0];
    const float* w_ih_f = (const float*)d_in[1];
    const float* w_hh_f = (const float*)d_in[2];
    const float* b_ih_f = (const float*)d_in[3];
    const float* b_hh_f = (const float*)d_in[4];
    const float* w_ih_b = (const float*)d_in[5];
    const float* w_hh_b = (const float*)d_in[6];
    const float* b_ih_b = (const float*)d_in[7];
    const float* b_hh_b = (const float*)d_in[8];
    float* out = (float*)d_out;

    const int proj_smem = TM * Is * sizeof(float) + 50 * 96 * sizeof(u64); // 64000 B

    static bool attr_done = false;
    if (!attr_done) {
        cudaFuncSetAttribute(proj_kernel,
                             cudaFuncAttributeMaxDynamicSharedMemorySize, proj_smem);
        attr_done = true;
    }

    dim3 pg(6, 49);           // persistent CTAs, ~2/SM
    proj_kernel<<<pg, 256, proj_smem>>>(x, w_ih_f, b_ih_f, w_ih_b, b_ih_b);
    scan_kernel<<<148, 288>>>(w_hh_f, b_hh_f, w_hh_b, b_hh_b, out);
}

// round 13
// speedup vs baseline: 1.4478x; 1.0014x over previous
#include <cuda_runtime.h>
#include <cstdint>

#define Hs 96
#define Is 100
#define Ts 512
#define Bs 512
#define Gs 288               // 3*H
#define Ms (Ts*Bs)           // 262144 rows
#define NB 7                 // batches per scan CTA
#define TM 64                // proj tile rows
#define NMT (Ms / TM)        // 4096 m-tiles

// Scratch for input projections: [dir][m][g]
__device__ float g_xproj[2][(size_t)Ms * Gs];

typedef unsigned long long u64;

__device__ __forceinline__ u64 fma2(u64 a, u64 b, u64 c) {
    u64 d;
    asm("fma.rn.f32x2 %0, %1, %2, %3;" : "=l"(d) : "l"(a), "l"(b), "l"(c));
    return d;
}
__device__ __forceinline__ float hsum2(u64 a) {
    float x, y;
    asm("mov.b64 {%0,%1}, %2;" : "=f"(x), "=f"(y) : "l"(a));
    return x + y;
}
__device__ __forceinline__ float sigm(float x) {
    return __fdividef(1.0f, 1.0f + __expf(-x));
}
__device__ __forceinline__ float tanh_(float x) {
    return 1.0f - __fdividef(2.0f, 1.0f + __expf(2.0f * x));
}

// ---------------------------------------------------------------------------
// Input projection — PERSISTENT + double-buffered prefetch + coalesced stores.
// grid (6, 49): bx -> (dir, 96-col group); each CTA loops m-tiles stride 49.
// 256 threads, 2 CTAs/SM. W tile loaded ONCE per CTA (transposed-paired
// wst[k2][g]: lane-consecutive u64 reads -> 2-wf spread, reused over 8 rows).
// Thread tile 8 rows x 3 cols with cg = tid&31: warp lanes cover 32
// consecutive g-columns -> ALL output stores are full-warp 128B coalesced.
// Next x tile prefetched into registers during the FMA loop.
// ---------------------------------------------------------------------------
__global__ __launch_bounds__(256, 2) void proj_kernel(
    const float* __restrict__ x,
    const float* __restrict__ wf, const float* __restrict__ bf,
    const float* __restrict__ wb, const float* __restrict__ bb)
{
    extern __shared__ __align__(16) float psm[];
    float* xs  = psm;                          // [TM][100]
    u64*   wst = (u64*)(psm + TM * Is);        // [50][96]

    const int bx  = blockIdx.x;                // 0..5
    const int dir = (bx >= 3);
    const int g0  = (dir ? bx - 3 : bx) * 96;
    const int tid = threadIdx.x;

    const float* __restrict__ w    = dir ? wb : wf;
    const float* __restrict__ bias = dir ? bb : bf;

    // W tile, once: wst[k2*96+g] = (W[g0+g][2k2], W[g0+g][2k2+1])
    for (int i = tid; i < 96 * 50; i += 256) {
        const int g = i / 50, k2 = i - g * 50;
        wst[k2 * 96 + g] = *(const u64*)(w + (size_t)(g0 + g) * Is + 2 * k2);
    }

    // First x tile (64 rows x 100 floats = 1600 float4, contiguous)
    int mt = blockIdx.y;
    {
        const float4* src = (const float4*)(x + (size_t)mt * TM * Is);
        float4* dst = (float4*)xs;
        for (int i = tid; i < TM * Is / 4; i += 256) dst[i] = src[i];
    }

    const int cg = tid & 31;     // col: g0 + cg + 32*c, c<3 (warp = 32 consec cols)
    const int rg = tid >> 5;     // row group: rows rg*8 + r, r<8

    float bv[3];
    #pragma unroll
    for (int c = 0; c < 3; c++) bv[c] = __ldg(&bias[g0 + cg + 32 * c]);

    __syncthreads();

    while (true) {
        const int mtn = mt + gridDim.y;
        const bool has_next = (mtn < NMT);

        // Prefetch next tile into registers (latency hidden by FMA loop)
        float4 pf[7];
        if (has_next) {
            const float4* src = (const float4*)(x + (size_t)mtn * TM * Is);
            #pragma unroll
            for (int j = 0; j < 7; j++) {
                const int idx = tid + j * 256;
                if (idx < TM * Is / 4) pf[j] = __ldg(&src[idx]);
            }
        }

        // Compute: 25 k4-iters, 48 fma2 each
        u64 acc[8][3];
        #pragma unroll
        for (int r = 0; r < 8; r++)
            #pragma unroll
            for (int c = 0; c < 3; c++) acc[r][c] = 0ull;

        #pragma unroll 5
        for (int k4 = 0; k4 < 25; k4++) {
            u64 wv0[3], wv1[3];
            #pragma unroll
            for (int c = 0; c < 3; c++) {
                wv0[c] = wst[(2 * k4)     * 96 + cg + 32 * c];
                wv1[c] = wst[(2 * k4 + 1) * 96 + cg + 32 * c];
            }
            #pragma unroll
            for (int r = 0; r < 8; r++) {
                const ulonglong2 xv = *(const ulonglong2*)&xs[(rg * 8 + r) * Is + 4 * k4];
                #pragma unroll
                for (int c = 0; c < 3; c++) {
                    acc[r][c] = fma2(xv.x, wv0[c], acc[r][c]);
                    acc[r][c] = fma2(xv.y, wv1[c], acc[r][c]);
                }
            }
        }

        // Stores: warp lanes -> 32 consecutive g-cols = 128B coalesced STG
        const size_t m0 = (size_t)mt * TM;
        #pragma unroll
        for (int c = 0; c < 3; c++) {
            const int gcol = g0 + cg + 32 * c;
            #pragma unroll
            for (int r = 0; r < 8; r++)
                g_xproj[dir][(m0 + rg * 8 + r) * Gs + gcol] = hsum2(acc[r][c]) + bv[c];
        }

        if (!has_next) break;
        __syncthreads();                       // everyone done reading xs
        {
            float4* dst = (float4*)xs;
            #pragma unroll
            for (int j = 0; j < 7; j++) {
                const int idx = tid + j * 256;
                if (idx < TM * Is / 4) dst[idx] = pf[j];
            }
        }
        __syncthreads();                       // new tile visible
        mt = mtn;
    }
}

// ---------------------------------------------------------------------------
// Recurrent scan (unchanged — at structural floor for this design).
// 148 CTAs (74 overlapping batch-groups of 7 x 2 dirs), 288 threads = 9 warps
// (minimum-wavefront design). Thread g owns W_hh row g in 48 u64 registers;
// h read warp-UNIFORM from smem.
// ---------------------------------------------------------------------------
__global__ __launch_bounds__(288, 1) void scan_kernel(
    const float* __restrict__ whf, const float* __restrict__ bhf,
    const float* __restrict__ whb, const float* __restrict__ bhb,
    float* __restrict__ out)
{
    __shared__ __align__(16) float hsh[NB][Hs];    // hidden state
    __shared__ float  rz[NB][2 * Hs];              // sigmoided r [0,96), z [96,192)
    __shared__ float2 dxn[NB][Hs];                 // (dot_n, xp_n)

    const int tid = threadIdx.x;                   // gate row g
    const int dir = blockIdx.x & 1;
    const int gi  = blockIdx.x >> 1;               // 0..73
    int b0 = 7 * gi; if (b0 > Bs - NB) b0 = Bs - NB;   // overlap-pad last group

    const float* __restrict__ wh = dir ? whb : whf;
    const float* __restrict__ bh = dir ? bhb : bhf;

    u64 w2[48];
    {
        const u64* wrow = (const u64*)(wh + tid * Hs);
        #pragma unroll
        for (int j = 0; j < 48; j++) w2[j] = __ldg(&wrow[j]);
    }
    const float bhv = __ldg(&bh[tid]);

    for (int i = tid; i < NB * Hs; i += 288) (&hsh[0][0])[i] = 0.0f;

    const float* __restrict__ xpb = g_xproj[dir];
    const int t_first = dir ? (Ts - 1) : 0;
    const int tstep   = dir ? -1 : 1;

    const bool is_n = (tid >= 2 * Hs);
    const int  gn   = tid - 2 * Hs;

    const int bb0 = (tid < Hs) ? 0 : (tid < 2 * Hs ? 1 : 2);
    const int i0  = tid - bb0 * Hs;

    float xc[NB], xn[NB];
    #pragma unroll
    for (int bbq = 0; bbq < NB; bbq++)
        xc[bbq] = __ldg(&xpb[((size_t)t_first * Bs + b0 + bbq) * Gs + tid]);

    __syncthreads();

    int tt = t_first;
    #pragma unroll 1
    for (int t = 0; t < Ts; t++) {
        const int tn = (t == Ts - 1) ? tt : (tt + tstep);
        #pragma unroll
        for (int bbq = 0; bbq < NB; bbq++)
            xn[bbq] = __ldg(&xpb[((size_t)tn * Bs + b0 + bbq) * Gs + tid]);

        u64 acc[NB];
        #pragma unroll
        for (int bbq = 0; bbq < NB; bbq++) acc[bbq] = 0ull;
        #pragma unroll
        for (int j = 0; j < 24; j++) {
            ulonglong2 hv[NB];
            #pragma unroll
            for (int bbq = 0; bbq < NB; bbq++)
                hv[bbq] = *(const ulonglong2*)&hsh[bbq][4 * j];
            #pragma unroll
            for (int bbq = 0; bbq < NB; bbq++) {
                acc[bbq] = fma2(w2[2 * j],     hv[bbq].x, acc[bbq]);
                acc[bbq] = fma2(w2[2 * j + 1], hv[bbq].y, acc[bbq]);
            }
        }

        if (!is_n) {
            #pragma unroll
            for (int bbq = 0; bbq < NB; bbq++)
                rz[bbq][tid] = sigm(xc[bbq] + hsum2(acc[bbq]) + bhv);
        } else {
            #pragma unroll
            for (int bbq = 0; bbq < NB; bbq++)
                dxn[bbq][gn] = make_float2(hsum2(acc[bbq]) + bhv, xc[bbq]);
        }
        __syncthreads();

        for (int bbq = bb0; bbq < NB; bbq += 3) {
            const float r = rz[bbq][i0];
            const float z = rz[bbq][Hs + i0];
            const float2 v = dxn[bbq][i0];
            const float n = tanh_(fmaf(r, v.x, v.y));
            const float hold = hsh[bbq][i0];
            const float hnew = fmaf(z, hold - n, n);
            hsh[bbq][i0] = hnew;
            out[((size_t)tt * Bs + b0 + bbq) * (2 * Hs) + dir * Hs + i0] = hnew;
        }
        __syncthreads();

        #pragma unroll
        for (int bbq = 0; bbq < NB; bbq++) xc[bbq] = xn[bbq];
        tt = tn;
    }
}

// ---------------------------------------------------------------------------
extern "C" void kernel_launch(void* const* d_in, const int* in_sizes, int n_in,
                              void* d_out, int out_size)
{
    const float* x      = (const float*)d_in[0];
    const float* w_ih_f = (const float*)d_in[1];
    const float* w_hh_f = (const float*)d_in[2];
    const float* b_ih_f = (const float*)d_in[3];
    const float* b_hh_f = (const float*)d_in[4];
    const float* w_ih_b = (const float*)d_in[5];
    const float* w_hh_b = (const float*)d_in[6];
    const float* b_ih_b = (const float*)d_in[7];
    const float* b_hh_b = (const float*)d_in[8];
    float* out = (float*)d_out;

    const int proj_smem = TM * Is * sizeof(float) + 50 * 96 * sizeof(u64); // 64000 B

    static bool attr_done = false;
    if (!attr_done) {
        cudaFuncSetAttribute(proj_kernel,
                             cudaFuncAttributeMaxDynamicSharedMemorySize, proj_smem);
        attr_done = true;
    }

    dim3 pg(6, 49);           // persistent CTAs, ~2/SM
    proj_kernel<<<pg, 256, proj_smem>>>(x, w_ih_f, b_ih_f, w_ih_b, b_ih_b);
    scan_kernel<<<148, 288>>>(w_hh_f, b_hh_f, w_hh_b, b_hh_b, out);
}

// round 15
// speedup vs baseline: 1.4823x; 1.0238x over previous
#include <cuda_runtime.h>
#include <cstdint>

#define Hs 96
#define Is 100
#define Ts 512
#define Bs 512
#define Gs 288               // 3*H
#define Ms (Ts*Bs)           // 262144 rows
#define NB 7                 // batches per scan CTA
#define TM 64                // proj tile rows
#define NMT (Ms / TM)        // 4096 m-tiles
#define XTILE4 (TM * Is / 4) // 1600 float4 per x tile

// Scratch for input projections: [dir][m][g]
__device__ float g_xproj[2][(size_t)Ms * Gs];

typedef unsigned long long u64;

__device__ __forceinline__ u64 fma2(u64 a, u64 b, u64 c) {
    u64 d;
    asm("fma.rn.f32x2 %0, %1, %2, %3;" : "=l"(d) : "l"(a), "l"(b), "l"(c));
    return d;
}
__device__ __forceinline__ float hsum2(u64 a) {
    float x, y;
    asm("mov.b64 {%0,%1}, %2;" : "=f"(x), "=f"(y) : "l"(a));
    return x + y;
}
__device__ __forceinline__ float sigm(float x) {
    return __fdividef(1.0f, 1.0f + __expf(-x));
}
__device__ __forceinline__ float tanh_(float x) {
    return 1.0f - __fdividef(2.0f, 1.0f + __expf(2.0f * x));
}
__device__ __forceinline__ uint32_t smem_u32(const void* p) {
    uint32_t a;
    asm("{ .reg .u64 t; cvta.to.shared.u64 t, %1; cvt.u32.u64 %0, t; }"
        : "=r"(a) : "l"(p));
    return a;
}
__device__ __forceinline__ void cp_async16(uint32_t dst, const void* src) {
    asm volatile("cp.async.ca.shared.global [%0], [%1], 16;"
                 :: "r"(dst), "l"(src));
}
__device__ __forceinline__ void cp_commit() {
    asm volatile("cp.async.commit_group;");
}
__device__ __forceinline__ void cp_wait0() {
    asm volatile("cp.async.wait_group 0;");
}

// ---------------------------------------------------------------------------
// Input projection — persistent, cp.async DOUBLE-BUFFERED ping-pong.
// grid (6, 49): bx -> (dir, 96-col group); each CTA loops m-tiles stride 49.
// 256 threads, 2 CTAs/SM (smem 89.6KB). W tile loaded ONCE (wq[k4][col]
// ulonglong2: one lane-consecutive LDS.128 per col per k4-iter).
// Per tile: issue 7x16B cp.async for NEXT tile into the idle buffer (DMA
// writes smem directly, overlaps the FMA loop), compute current buffer,
// coalesced stores, wait_group + ONE __syncthreads, swap.
// Thread tile 8 rows x 3 cols; cg = tid&31 -> all STG full-warp coalesced.
// ---------------------------------------------------------------------------
__global__ __launch_bounds__(256, 2) void proj_kernel(
    const float* __restrict__ x,
    const float* __restrict__ wf, const float* __restrict__ bf,
    const float* __restrict__ wb, const float* __restrict__ bb)
{
    extern __shared__ __align__(16) float psm[];
    float* xs0 = psm;                                  // [TM][100]
    float* xs1 = psm + TM * Is;                        // [TM][100]
    ulonglong2* wq = (ulonglong2*)(psm + 2 * TM * Is); // [25][96]

    const int bx  = blockIdx.x;                        // 0..5
    const int dir = (bx >= 3);
    const int g0  = (dir ? bx - 3 : bx) * 96;
    const int tid = threadIdx.x;

    const float* __restrict__ w    = dir ? wb : wf;
    const float* __restrict__ bias = dir ? bb : bf;

    // W tile once: wq[k4*96+col] = 16B k4-window of W row (g0+col)
    for (int i = tid; i < 96 * 25; i += 256) {
        const int col = i % 96, k4 = i / 96;
        wq[k4 * 96 + col] = *(const ulonglong2*)(w + (size_t)(g0 + col) * Is + 4 * k4);
    }

    // First x tile -> buffer 0 (cp.async, then drain)
    int mt = blockIdx.y;
    {
        const uint32_t dst = smem_u32(xs0);
        const char* src = (const char*)(x + (size_t)mt * TM * Is);
        #pragma unroll
        for (int j = 0; j < 7; j++) {
            const int idx = tid + j * 256;
            if (idx < XTILE4) cp_async16(dst + idx * 16, src + idx * 16);
        }
        cp_commit();
    }

    const int cg = tid & 31;     // col: g0 + cg + 32*c (warp = 32 consec cols)
    const int rg = tid >> 5;     // rows rg*8 + r (warp-uniform)

    float bv[3];
    #pragma unroll
    for (int c = 0; c < 3; c++) bv[c] = __ldg(&bias[g0 + cg + 32 * c]);

    cp_wait0();
    __syncthreads();

    int p = 0;
    while (true) {
        const int mtn = mt + gridDim.y;
        const bool has_next = (mtn < NMT);

        float* cur = p ? xs1 : xs0;
        float* nxt = p ? xs0 : xs1;

        // Kick off next tile's async copy into the idle buffer
        if (has_next) {
            const uint32_t dst = smem_u32(nxt);
            const char* src = (const char*)(x + (size_t)mtn * TM * Is);
            #pragma unroll
            for (int j = 0; j < 7; j++) {
                const int idx = tid + j * 256;
                if (idx < XTILE4) cp_async16(dst + idx * 16, src + idx * 16);
            }
            cp_commit();
        }

        // Compute: 25 k4-iters, 48 fma2 each
        u64 acc[8][3];
        #pragma unroll
        for (int r = 0; r < 8; r++)
            #pragma unroll
            for (int c = 0; c < 3; c++) acc[r][c] = 0ull;

        #pragma unroll 5
        for (int k4 = 0; k4 < 25; k4++) {
            ulonglong2 wv[3];
            #pragma unroll
            for (int c = 0; c < 3; c++)
                wv[c] = wq[k4 * 96 + cg + 32 * c];
            #pragma unroll
            for (int r = 0; r < 8; r++) {
                const ulonglong2 xv = *(const ulonglong2*)&cur[(rg * 8 + r) * Is + 4 * k4];
                #pragma unroll
                for (int c = 0; c < 3; c++) {
                    acc[r][c] = fma2(xv.x, wv[c].x, acc[r][c]);
                    acc[r][c] = fma2(xv.y, wv[c].y, acc[r][c]);
                }
            }
        }

        // Stores: warp lanes -> 32 consecutive g-cols = 128B coalesced STG
        const size_t m0 = (size_t)mt * TM;
        #pragma unroll
        for (int c = 0; c < 3; c++) {
            const int gcol = g0 + cg + 32 * c;
            #pragma unroll
            for (int r = 0; r < 8; r++)
                g_xproj[dir][(m0 + rg * 8 + r) * Gs + gcol] = hsum2(acc[r][c]) + bv[c];
        }

        if (!has_next) break;
        cp_wait0();              // next tile landed in smem
        __syncthreads();         // ... and everyone is done reading cur
        p ^= 1;
        mt = mtn;
    }
}

// ---------------------------------------------------------------------------
// Recurrent scan (FROZEN — at structural floor for this design).
// 148 CTAs (74 overlapping batch-groups of 7 x 2 dirs), 288 threads = 9 warps
// (minimum-wavefront design). Thread g owns W_hh row g in 48 u64 registers;
// h read warp-UNIFORM from smem.
// ---------------------------------------------------------------------------
__global__ __launch_bounds__(288, 1) void scan_kernel(
    const float* __restrict__ whf, const float* __restrict__ bhf,
    const float* __restrict__ whb, const float* __restrict__ bhb,
    float* __restrict__ out)
{
    __shared__ __align__(16) float hsh[NB][Hs];    // hidden state
    __shared__ float  rz[NB][2 * Hs];              // sigmoided r [0,96), z [96,192)
    __shared__ float2 dxn[NB][Hs];                 // (dot_n, xp_n)

    const int tid = threadIdx.x;                   // gate row g
    const int dir = blockIdx.x & 1;
    const int gi  = blockIdx.x >> 1;               // 0..73
    int b0 = 7 * gi; if (b0 > Bs - NB) b0 = Bs - NB;   // overlap-pad last group

    const float* __restrict__ wh = dir ? whb : whf;
    const float* __restrict__ bh = dir ? bhb : bhf;

    u64 w2[48];
    {
        const u64* wrow = (const u64*)(wh + tid * Hs);
        #pragma unroll
        for (int j = 0; j < 48; j++) w2[j] = __ldg(&wrow[j]);
    }
    const float bhv = __ldg(&bh[tid]);

    for (int i = tid; i < NB * Hs; i += 288) (&hsh[0][0])[i] = 0.0f;

    const float* __restrict__ xpb = g_xproj[dir];
    const int t_first = dir ? (Ts - 1) : 0;
    const int tstep   = dir ? -1 : 1;

    const bool is_n = (tid >= 2 * Hs);
    const int  gn   = tid - 2 * Hs;

    const int bb0 = (tid < Hs) ? 0 : (tid < 2 * Hs ? 1 : 2);
    const int i0  = tid - bb0 * Hs;

    float xc[NB], xn[NB];
    #pragma unroll
    for (int bbq = 0; bbq < NB; bbq++)
        xc[bbq] = __ldg(&xpb[((size_t)t_first * Bs + b0 + bbq) * Gs + tid]);

    __syncthreads();

    int tt = t_first;
    #pragma unroll 1
    for (int t = 0; t < Ts; t++) {
        const int tn = (t == Ts - 1) ? tt : (tt + tstep);
        #pragma unroll
        for (int bbq = 0; bbq < NB; bbq++)
            xn[bbq] = __ldg(&xpb[((size_t)tn * Bs + b0 + bbq) * Gs + tid]);

        u64 acc[NB];
        #pragma unroll
        for (int bbq = 0; bbq < NB; bbq++) acc[bbq] = 0ull;
        #pragma unroll
        for (int j = 0; j < 24; j++) {
            ulonglong2 hv[NB];
            #pragma unroll
            for (int bbq = 0; bbq < NB; bbq++)
                hv[bbq] = *(const ulonglong2*)&hsh[bbq][4 * j];
            #pragma unroll
            for (int bbq = 0; bbq < NB; bbq++) {
                acc[bbq] = fma2(w2[2 * j],     hv[bbq].x, acc[bbq]);
                acc[bbq] = fma2(w2[2 * j + 1], hv[bbq].y, acc[bbq]);
            }
        }

        if (!is_n) {
            #pragma unroll
            for (int bbq = 0; bbq < NB; bbq++)
                rz[bbq][tid] = sigm(xc[bbq] + hsum2(acc[bbq]) + bhv);
        } else {
            #pragma unroll
            for (int bbq = 0; bbq < NB; bbq++)
                dxn[bbq][gn] = make_float2(hsum2(acc[bbq]) + bhv, xc[bbq]);
        }
        __syncthreads();

        for (int bbq = bb0; bbq < NB; bbq += 3) {
            const float r = rz[bbq][i0];
            const float z = rz[bbq][Hs + i0];
            const float2 v = dxn[bbq][i0];
            const float n = tanh_(fmaf(r, v.x, v.y));
            const float hold = hsh[bbq][i0];
            const float hnew = fmaf(z, hold - n, n);
            hsh[bbq][i0] = hnew;
            out[((size_t)tt * Bs + b0 + bbq) * (2 * Hs) + dir * Hs + i0] = hnew;
        }
        __syncthreads();

        #pragma unroll
        for (int bbq = 0; bbq < NB; bbq++) xc[bbq] = xn[bbq];
        tt = tn;
    }
}

// ---------------------------------------------------------------------------
extern "C" void kernel_launch(void* const* d_in, const int* in_sizes, int n_in,
                              void* d_out, int out_size)
{
    const float* x      = (const float*)d_in[0];
    const float* w_ih_f = (const float*)d_in[1];
    const float* w_hh_f = (const float*)d_in[2];
    const float* b_ih_f = (const float*)d_in[3];
    const float* b_hh_f = (const float*)d_in[4];
    const float* w_ih_b = (const float*)d_in[5];
    const float* w_hh_b = (const float*)d_in[6];
    const float* b_ih_b = (const float*)d_in[7];
    const float* b_hh_b = (const float*)d_in[8];
    float* out = (float*)d_out;

    // 2 x-tile buffers + W tile = 51200 + 38400 = 89600 B
    const int proj_smem = 2 * TM * Is * sizeof(float) + 25 * 96 * sizeof(ulonglong2);

    static bool attr_done = false;
    if (!attr_done) {
        cudaFuncSetAttribute(proj_kernel,
                             cudaFuncAttributeMaxDynamicSharedMemorySize, proj_smem);
        attr_done = true;
    }

    dim3 pg(6, 49);           // persistent CTAs, 2/SM
    proj_kernel<<<pg, 256, proj_smem>>>(x, w_ih_f, b_ih_f, w_ih_b, b_ih_b);
    scan_kernel<<<148, 288>>>(w_hh_f, b_hh_f, w_hh_b, b_hh_b, out);
}